// round 2
// baseline (speedup 1.0000x reference)
#include <cuda_runtime.h>
#include <math.h>
#include <stdint.h>

#define U_CNT 30000
#define I_CNT 60000
#define G_CNT 2000
#define EMBD  64
#define N_UI  (U_CNT + I_CNT)      // 90000
#define N_TOT (N_UI + G_CNT)       // 92000

// ---------------- device scratch (static, no allocation) ----------------
__device__ float g_cur [N_UI * EMBD];
__device__ float g_msgu[G_CNT * EMBD];
__device__ float g_msgi[G_CNT * EMBD];
__device__ float g_msg [G_CNT * EMBD];

// ---------------- packed f32x2 helpers (Blackwell 2xFP32 pipe) ----------------
__device__ __forceinline__ uint64_t pack2(float lo, float hi) {
    uint64_t r;
    asm("mov.b64 %0, {%1, %2};" : "=l"(r) : "f"(lo), "f"(hi));
    return r;
}
__device__ __forceinline__ void ffma2(uint64_t& d, uint64_t a, uint64_t b) {
    asm("fma.rn.f32x2 %0, %1, %2, %0;" : "+l"(d) : "l"(a), "l"(b));
}
__device__ __forceinline__ float2 unpack2(uint64_t v) {
    float2 f;
    asm("mov.b64 {%0, %1}, %2;" : "=f"(f.x), "=f"(f.y) : "l"(v));
    return f;
}

// ---------------- init: cur = concat(user,item); out = [cur ; group_emb] ----------------
__global__ void init_kernel(const float* __restrict__ ue,
                            const float* __restrict__ ie,
                            const float* __restrict__ ge,
                            float* __restrict__ out,
                            float* __restrict__ cur)
{
    int i = blockIdx.x * blockDim.x + threadIdx.x;
    const int totUI = N_UI * EMBD;
    if (i < totUI) {
        float v = (i < U_CNT * EMBD) ? ue[i] : ie[i - U_CNT * EMBD];
        cur[i] = v;
        out[i] = v;
    } else if (i < totUI + G_CNT * EMBD) {
        out[i] = ge[i - totUI];
    }
}

__global__ void zero_msgs(float* __restrict__ mu, float* __restrict__ mi)
{
    int i = blockIdx.x * blockDim.x + threadIdx.x;
    if (i < G_CNT * EMBD) { mu[i] = 0.f; mi[i] = 0.f; }
}

// ---------------- fp32 tiled GEMM, C[M,64] = A[M,K] @ B[K,64] ----------------
// BM=128, BN=64, BK=32, 256 threads, 8x4 microtile, FFMA2 inner loop.
// A loaded coalesced (LDG.128 along K), transposed into smem.
// ATOMIC=true : split-K partials accumulated with atomicAdd into C (pre-zeroed).
// ATOMIC=false: full-K per block; C[idx]=acc and outAdd[idx]+=acc (fused epilogue).
template <bool ATOMIC>
__global__ __launch_bounds__(256, 2)
void gemm_n64(const float* __restrict__ A, const float* __restrict__ B,
              float* __restrict__ C, float* __restrict__ outAdd,
              int M, int K, int kChunk)
{
    __shared__ float As[32][136];   // [k][m], BM=128 + pad 8 (row = 544B, 32B-aligned)
    __shared__ float Bs[32][64];    // [k][n]

    const int m0   = blockIdx.x * 128;
    const int k0   = blockIdx.y * kChunk;
    const int kEnd = min(k0 + kChunk, K);

    const int tid = threadIdx.x;
    const int tx  = tid & 15;     // 0..15 -> 4 cols each
    const int ty  = tid >> 4;     // 0..15 -> 8 rows each

    // A-load mapping: coalesced along K
    const int lr  = tid >> 3;     // 0..31 (row within pass)
    const int lc4 = tid & 7;      // 0..7  (float4 index along k)

    uint64_t acc[4][4];
#pragma unroll
    for (int i = 0; i < 4; i++)
#pragma unroll
        for (int j = 0; j < 4; j++) acc[i][j] = 0ULL;

    for (int kb = k0; kb < kEnd; kb += 32) {
        // ---- load A tile (128 rows x 32 k), coalesced, transpose into As[k][m]
#pragma unroll
        for (int i = 0; i < 4; i++) {
            const int m  = m0 + lr + 32 * i;
            const int kg = kb + lc4 * 4;
            float4 v = make_float4(0.f, 0.f, 0.f, 0.f);
            if (m < M) {
                if (kg + 3 < kEnd) {
                    v = *(const float4*)&A[(size_t)m * K + kg];
                } else {
                    float* pv = (float*)&v;
#pragma unroll
                    for (int q = 0; q < 4; q++)
                        if (kg + q < kEnd) pv[q] = A[(size_t)m * K + kg + q];
                }
            }
            const int r = lr + 32 * i;
            As[lc4 * 4 + 0][r] = v.x;
            As[lc4 * 4 + 1][r] = v.y;
            As[lc4 * 4 + 2][r] = v.z;
            As[lc4 * 4 + 3][r] = v.w;
        }
        // ---- load B tile (32 k x 64 n), coalesced, no transpose
#pragma unroll
        for (int i = 0; i < 2; i++) {
            const int kr = (tid >> 4) + 16 * i;
            const int kg = kb + kr;
            const int n4 = (tid & 15) * 4;
            float4 v = make_float4(0.f, 0.f, 0.f, 0.f);
            if (kg < kEnd) v = *(const float4*)&B[(size_t)kg * 64 + n4];
            *(float4*)&Bs[kr][n4] = v;
        }
        __syncthreads();

#pragma unroll
        for (int kk = 0; kk < 32; kk++) {
            // 8 A values (rows ty*8 .. ty*8+7) as 4 packed pairs
            const ulonglong2 a01 = *(const ulonglong2*)&As[kk][ty * 8];
            const ulonglong2 a23 = *(const ulonglong2*)&As[kk][ty * 8 + 4];
            // 4 B values, each duplicated into a pair
            const float4 b = *(const float4*)&Bs[kk][tx * 4];
            const uint64_t bb0 = pack2(b.x, b.x);
            const uint64_t bb1 = pack2(b.y, b.y);
            const uint64_t bb2 = pack2(b.z, b.z);
            const uint64_t bb3 = pack2(b.w, b.w);

            ffma2(acc[0][0], a01.x, bb0);
            ffma2(acc[0][1], a01.x, bb1);
            ffma2(acc[0][2], a01.x, bb2);
            ffma2(acc[0][3], a01.x, bb3);
            ffma2(acc[1][0], a01.y, bb0);
            ffma2(acc[1][1], a01.y, bb1);
            ffma2(acc[1][2], a01.y, bb2);
            ffma2(acc[1][3], a01.y, bb3);
            ffma2(acc[2][0], a23.x, bb0);
            ffma2(acc[2][1], a23.x, bb1);
            ffma2(acc[2][2], a23.x, bb2);
            ffma2(acc[2][3], a23.x, bb3);
            ffma2(acc[3][0], a23.y, bb0);
            ffma2(acc[3][1], a23.y, bb1);
            ffma2(acc[3][2], a23.y, bb2);
            ffma2(acc[3][3], a23.y, bb3);
        }
        __syncthreads();
    }

    // ---- epilogue: acc[ip][j] holds rows (ty*8 + 2*ip, ty*8 + 2*ip + 1)
#pragma unroll
    for (int ip = 0; ip < 4; ip++) {
        const int m_lo = m0 + ty * 8 + 2 * ip;
#pragma unroll
        for (int j = 0; j < 4; j++) {
            const float2 v = unpack2(acc[ip][j]);
            const int n = tx * 4 + j;
            if (m_lo < M) {
                const int idx = m_lo * 64 + n;
                if (ATOMIC) atomicAdd(&C[idx], v.x);
                else { C[idx] = v.x; outAdd[idx] += v.x; }
            }
            if (m_lo + 1 < M) {
                const int idx = (m_lo + 1) * 64 + n;
                if (ATOMIC) atomicAdd(&C[idx], v.y);
                else { C[idx] = v.y; outAdd[idx] += v.y; }
            }
        }
    }
}

// ---------------- per-group attention + MLP fusion ----------------
__global__ __launch_bounds__(256)
void group_kernel(const float* __restrict__ mu, const float* __restrict__ mi,
                  const float* __restrict__ gemb,
                  const float* __restrict__ qc_w1, const float* __restrict__ qc_b1,
                  const float* __restrict__ qc_w2,
                  const float* __restrict__ user_w, const float* __restrict__ user_b,
                  const float* __restrict__ item_w, const float* __restrict__ item_b,
                  float* __restrict__ msg, float* __restrict__ out)
{
    const int sub = threadIdx.x >> 6;
    const int j   = threadIdx.x & 63;
    const int g   = blockIdx.x * 4 + sub;

    __shared__ float xu[4][64], xi[4][64], ge[4][64];
    __shared__ float tu[4][64], ti[4][64];
    __shared__ float du[4][64], di[4][64];
    __shared__ float redA[4][64], redB[4][64];

    xu[sub][j] = mu[g * 64 + j];
    xi[sub][j] = mi[g * 64 + j];
    ge[sub][j] = gemb[g * 64 + j];
    __syncthreads();

    {
        float hu = qc_b1[j], hi = qc_b1[j];
#pragma unroll 8
        for (int k = 0; k < 64; k++) {
            float w = qc_w1[k * 64 + j];
            hu = fmaf(xu[sub][k], w, hu);
            hi = fmaf(xi[sub][k], w, hi);
        }
        tu[sub][j] = tanhf(hu);
        ti[sub][j] = tanhf(hi);
    }
    __syncthreads();

    {
        float w2 = qc_w2[j];
        redA[sub][j] = tu[sub][j] * w2;
        redB[sub][j] = ti[sub][j] * w2;
    }
    __syncthreads();
    for (int s = 32; s > 0; s >>= 1) {
        if (j < s) {
            redA[sub][j] += redA[sub][j + s];
            redB[sub][j] += redB[sub][j + s];
        }
        __syncthreads();
    }
    const float qu = redA[sub][0];
    const float qi = redB[sub][0];

    const float mx = fmaxf(qu, qi);
    const float eu = expf(qu - mx);
    const float ei = expf(qi - mx);
    const float w0  = eu / (eu + ei);
    const float w1v = ei / (eu + ei);

    const float c = w0 * xu[sub][j] + w1v * xi[sub][j];
    du[sub][j] = xu[sub][j] - c;
    di[sub][j] = xi[sub][j] - c;
    __syncthreads();

    float u2 = user_b[j];
    float i2 = item_b[j];
#pragma unroll 8
    for (int k = 0; k < 64; k++) {
        u2 = fmaf(du[sub][k], user_w[k * 64 + j], u2);
        i2 = fmaf(di[sub][k], item_w[k * 64 + j], i2);
    }
#pragma unroll 8
    for (int k = 0; k < 64; k++) {
        float gv = ge[sub][k];
        u2 = fmaf(gv, user_w[(64 + k) * 64 + j], u2);
        i2 = fmaf(gv, item_w[(64 + k) * 64 + j], i2);
    }

    const float m = u2 + i2 + c;
    msg[g * 64 + j] = m;
    out[N_UI * 64 + g * 64 + j] += m;
}

// ---------------- launch ----------------
extern "C" void kernel_launch(void* const* d_in, const int* in_sizes, int n_in,
                              void* d_out, int out_size)
{
    const float* user_emb   = (const float*)d_in[0];
    const float* item_emb   = (const float*)d_in[1];
    const float* group_emb  = (const float*)d_in[2];
    const float* user_hyper = (const float*)d_in[3];
    const float* item_hyper = (const float*)d_in[4];
    const float* full_hyper = (const float*)d_in[5];

    int wbase = 6;
    if (n_in >= 15 && in_sizes[6] == 1 && in_sizes[7] == 1) wbase = 8;
    const float* qc_w1  = (const float*)d_in[wbase + 0];
    const float* qc_b1  = (const float*)d_in[wbase + 1];
    const float* qc_w2  = (const float*)d_in[wbase + 2];
    const float* user_w = (const float*)d_in[wbase + 3];
    const float* user_b = (const float*)d_in[wbase + 4];
    const float* item_w = (const float*)d_in[wbase + 5];
    const float* item_b = (const float*)d_in[wbase + 6];

    float* out = (float*)d_out;

    float *cur, *mu, *mi, *mg;
    cudaGetSymbolAddress((void**)&cur, g_cur);
    cudaGetSymbolAddress((void**)&mu,  g_msgu);
    cudaGetSymbolAddress((void**)&mi,  g_msgi);
    cudaGetSymbolAddress((void**)&mg,  g_msg);

    init_kernel<<<(N_TOT * EMBD + 255) / 256, 256>>>(user_emb, item_emb, group_emb, out, cur);

    const int KC_U = 1280;   // 24 splits over K=30000
    const int KC_I = 2560;   // 24 splits over K=60000

    for (int l = 0; l < 2; l++) {
        zero_msgs<<<(G_CNT * EMBD + 255) / 256, 256>>>(mu, mi);

        // msg_u = user_hyper @ cur[:U]
        {
            dim3 grid((G_CNT + 127) / 128, (U_CNT + KC_U - 1) / KC_U);
            gemm_n64<true><<<grid, 256>>>(user_hyper, cur, mu, nullptr,
                                          G_CNT, U_CNT, KC_U);
        }
        // msg_i = item_hyper @ cur[U:]
        {
            dim3 grid((G_CNT + 127) / 128, (I_CNT + KC_I - 1) / KC_I);
            gemm_n64<true><<<grid, 256>>>(item_hyper, cur + (size_t)U_CNT * EMBD, mi, nullptr,
                                          G_CNT, I_CNT, KC_I);
        }
        // attention + MLPs -> msg ; out_he += msg
        group_kernel<<<G_CNT / 4, 256>>>(mu, mi, group_emb,
                                         qc_w1 + l * 64 * 64, qc_b1 + l * 64,
                                         qc_w2 + l * 64,
                                         user_w + l * 128 * 64, user_b + l * 64,
                                         item_w + l * 128 * 64, item_b + l * 64,
                                         mg, out);
        // cur = full_hyper @ msg ; out[:90000*64] += cur
        {
            dim3 grid((N_UI + 127) / 128, 1);
            gemm_n64<false><<<grid, 256>>>(full_hyper, mg, cur, out,
                                           N_UI, G_CNT, G_CNT);
        }
    }
    (void)in_sizes; (void)n_in; (void)out_size;
}

// round 3
// speedup vs baseline: 1.4027x; 1.4027x over previous
#include <cuda_runtime.h>
#include <math.h>
#include <stdint.h>

#define U_CNT 30000
#define I_CNT 60000
#define G_CNT 2000
#define EMBD  64
#define N_UI  (U_CNT + I_CNT)      // 90000
#define N_TOT (N_UI + G_CNT)       // 92000

// ---------------- device scratch (static, no allocation) ----------------
__device__ float g_cur [N_UI * EMBD];
__device__ float g_msgu[G_CNT * EMBD];
__device__ float g_msgi[G_CNT * EMBD];
__device__ float g_msg [G_CNT * EMBD];

// ---------------- packed f32x2 helpers (Blackwell 2xFP32 pipe) ----------------
__device__ __forceinline__ uint64_t pack2(float lo, float hi) {
    uint64_t r;
    asm("mov.b64 %0, {%1, %2};" : "=l"(r) : "f"(lo), "f"(hi));
    return r;
}
__device__ __forceinline__ void ffma2(uint64_t& d, uint64_t a, uint64_t b) {
    asm("fma.rn.f32x2 %0, %1, %2, %0;" : "+l"(d) : "l"(a), "l"(b));
}
__device__ __forceinline__ float2 unpack2(uint64_t v) {
    float2 f;
    asm("mov.b64 {%0, %1}, %2;" : "=f"(f.x), "=f"(f.y) : "l"(v));
    return f;
}

// ---------------- init: cur = concat(user,item); out = [cur ; group_emb] ----------------
__global__ void init_kernel(const float* __restrict__ ue,
                            const float* __restrict__ ie,
                            const float* __restrict__ ge,
                            float* __restrict__ out,
                            float* __restrict__ cur)
{
    int i = blockIdx.x * blockDim.x + threadIdx.x;
    const int totUI = N_UI * EMBD;
    if (i < totUI) {
        float v = (i < U_CNT * EMBD) ? ue[i] : ie[i - U_CNT * EMBD];
        cur[i] = v;
        out[i] = v;
    } else if (i < totUI + G_CNT * EMBD) {
        out[i] = ge[i - totUI];
    }
}

__global__ void zero_msgs(float* __restrict__ mu, float* __restrict__ mi)
{
    int i = blockIdx.x * blockDim.x + threadIdx.x;
    if (i < G_CNT * EMBD) { mu[i] = 0.f; mi[i] = 0.f; }
}

// ---------------- fp32 tiled GEMM, C[M,64] = A[M,K] @ B[K,64] ----------------
// BM=128, BN=64, BK=32, 256 threads, 8x4 microtile, FFMA2 inner loop.
// A loaded coalesced (LDG.128 along K), transposed into smem.
// ATOMIC=true : split-K partials accumulated with atomicAdd into C (pre-zeroed).
// ATOMIC=false: full-K per block; C[idx]=acc and outAdd[idx]+=acc (fused epilogue).
template <bool ATOMIC>
__global__ __launch_bounds__(256, 2)
void gemm_n64(const float* __restrict__ A, const float* __restrict__ B,
              float* __restrict__ C, float* __restrict__ outAdd,
              int M, int K, int kChunk)
{
    __shared__ float As[32][136];   // [k][m], BM=128 + pad 8 (row = 544B, 32B-aligned)
    __shared__ float Bs[32][64];    // [k][n]

    const int m0   = blockIdx.x * 128;
    const int k0   = blockIdx.y * kChunk;
    const int kEnd = min(k0 + kChunk, K);

    const int tid = threadIdx.x;
    const int tx  = tid & 15;     // 0..15 -> 4 cols each
    const int ty  = tid >> 4;     // 0..15 -> 8 rows each

    // A-load mapping: coalesced along K
    const int lr  = tid >> 3;     // 0..31 (row within pass)
    const int lc4 = tid & 7;      // 0..7  (float4 index along k)

    uint64_t acc[4][4];
#pragma unroll
    for (int i = 0; i < 4; i++)
#pragma unroll
        for (int j = 0; j < 4; j++) acc[i][j] = 0ULL;

    for (int kb = k0; kb < kEnd; kb += 32) {
        // ---- load A tile (128 rows x 32 k), coalesced, transpose into As[k][m]
#pragma unroll
        for (int i = 0; i < 4; i++) {
            const int m  = m0 + lr + 32 * i;
            const int kg = kb + lc4 * 4;
            float4 v = make_float4(0.f, 0.f, 0.f, 0.f);
            if (m < M) {
                if (kg + 3 < kEnd) {
                    v = *(const float4*)&A[(size_t)m * K + kg];
                } else {
                    float* pv = (float*)&v;
#pragma unroll
                    for (int q = 0; q < 4; q++)
                        if (kg + q < kEnd) pv[q] = A[(size_t)m * K + kg + q];
                }
            }
            const int r = lr + 32 * i;
            As[lc4 * 4 + 0][r] = v.x;
            As[lc4 * 4 + 1][r] = v.y;
            As[lc4 * 4 + 2][r] = v.z;
            As[lc4 * 4 + 3][r] = v.w;
        }
        // ---- load B tile (32 k x 64 n), coalesced, no transpose
#pragma unroll
        for (int i = 0; i < 2; i++) {
            const int kr = (tid >> 4) + 16 * i;
            const int kg = kb + kr;
            const int n4 = (tid & 15) * 4;
            float4 v = make_float4(0.f, 0.f, 0.f, 0.f);
            if (kg < kEnd) v = *(const float4*)&B[(size_t)kg * 64 + n4];
            *(float4*)&Bs[kr][n4] = v;
        }
        __syncthreads();

#pragma unroll
        for (int kk = 0; kk < 32; kk++) {
            // 8 A values (rows ty*8 .. ty*8+7) as 4 packed pairs
            const ulonglong2 a01 = *(const ulonglong2*)&As[kk][ty * 8];
            const ulonglong2 a23 = *(const ulonglong2*)&As[kk][ty * 8 + 4];
            // 4 B values, each duplicated into a pair
            const float4 b = *(const float4*)&Bs[kk][tx * 4];
            const uint64_t bb0 = pack2(b.x, b.x);
            const uint64_t bb1 = pack2(b.y, b.y);
            const uint64_t bb2 = pack2(b.z, b.z);
            const uint64_t bb3 = pack2(b.w, b.w);

            ffma2(acc[0][0], a01.x, bb0);
            ffma2(acc[0][1], a01.x, bb1);
            ffma2(acc[0][2], a01.x, bb2);
            ffma2(acc[0][3], a01.x, bb3);
            ffma2(acc[1][0], a01.y, bb0);
            ffma2(acc[1][1], a01.y, bb1);
            ffma2(acc[1][2], a01.y, bb2);
            ffma2(acc[1][3], a01.y, bb3);
            ffma2(acc[2][0], a23.x, bb0);
            ffma2(acc[2][1], a23.x, bb1);
            ffma2(acc[2][2], a23.x, bb2);
            ffma2(acc[2][3], a23.x, bb3);
            ffma2(acc[3][0], a23.y, bb0);
            ffma2(acc[3][1], a23.y, bb1);
            ffma2(acc[3][2], a23.y, bb2);
            ffma2(acc[3][3], a23.y, bb3);
        }
        __syncthreads();
    }

    // ---- epilogue: acc[ip][j] holds rows (ty*8 + 2*ip, ty*8 + 2*ip + 1)
#pragma unroll
    for (int ip = 0; ip < 4; ip++) {
        const int m_lo = m0 + ty * 8 + 2 * ip;
#pragma unroll
        for (int j = 0; j < 4; j++) {
            const float2 v = unpack2(acc[ip][j]);
            const int n = tx * 4 + j;
            if (m_lo < M) {
                const int idx = m_lo * 64 + n;
                if (ATOMIC) atomicAdd(&C[idx], v.x);
                else { C[idx] = v.x; outAdd[idx] += v.x; }
            }
            if (m_lo + 1 < M) {
                const int idx = (m_lo + 1) * 64 + n;
                if (ATOMIC) atomicAdd(&C[idx], v.y);
                else { C[idx] = v.y; outAdd[idx] += v.y; }
            }
        }
    }
}

// ---------------- per-group attention + MLP fusion ----------------
__global__ __launch_bounds__(256)
void group_kernel(const float* __restrict__ mu, const float* __restrict__ mi,
                  const float* __restrict__ gemb,
                  const float* __restrict__ qc_w1, const float* __restrict__ qc_b1,
                  const float* __restrict__ qc_w2,
                  const float* __restrict__ user_w, const float* __restrict__ user_b,
                  const float* __restrict__ item_w, const float* __restrict__ item_b,
                  float* __restrict__ msg, float* __restrict__ out)
{
    const int sub = threadIdx.x >> 6;
    const int j   = threadIdx.x & 63;
    const int g   = blockIdx.x * 4 + sub;

    __shared__ float xu[4][64], xi[4][64], ge[4][64];
    __shared__ float tu[4][64], ti[4][64];
    __shared__ float du[4][64], di[4][64];
    __shared__ float redA[4][64], redB[4][64];

    xu[sub][j] = mu[g * 64 + j];
    xi[sub][j] = mi[g * 64 + j];
    ge[sub][j] = gemb[g * 64 + j];
    __syncthreads();

    {
        float hu = qc_b1[j], hi = qc_b1[j];
#pragma unroll 8
        for (int k = 0; k < 64; k++) {
            float w = qc_w1[k * 64 + j];
            hu = fmaf(xu[sub][k], w, hu);
            hi = fmaf(xi[sub][k], w, hi);
        }
        tu[sub][j] = tanhf(hu);
        ti[sub][j] = tanhf(hi);
    }
    __syncthreads();

    {
        float w2 = qc_w2[j];
        redA[sub][j] = tu[sub][j] * w2;
        redB[sub][j] = ti[sub][j] * w2;
    }
    __syncthreads();
    for (int s = 32; s > 0; s >>= 1) {
        if (j < s) {
            redA[sub][j] += redA[sub][j + s];
            redB[sub][j] += redB[sub][j + s];
        }
        __syncthreads();
    }
    const float qu = redA[sub][0];
    const float qi = redB[sub][0];

    const float mx = fmaxf(qu, qi);
    const float eu = expf(qu - mx);
    const float ei = expf(qi - mx);
    const float w0  = eu / (eu + ei);
    const float w1v = ei / (eu + ei);

    const float c = w0 * xu[sub][j] + w1v * xi[sub][j];
    du[sub][j] = xu[sub][j] - c;
    di[sub][j] = xi[sub][j] - c;
    __syncthreads();

    float u2 = user_b[j];
    float i2 = item_b[j];
#pragma unroll 8
    for (int k = 0; k < 64; k++) {
        u2 = fmaf(du[sub][k], user_w[k * 64 + j], u2);
        i2 = fmaf(di[sub][k], item_w[k * 64 + j], i2);
    }
#pragma unroll 8
    for (int k = 0; k < 64; k++) {
        float gv = ge[sub][k];
        u2 = fmaf(gv, user_w[(64 + k) * 64 + j], u2);
        i2 = fmaf(gv, item_w[(64 + k) * 64 + j], i2);
    }

    const float m = u2 + i2 + c;
    msg[g * 64 + j] = m;
    out[N_UI * 64 + g * 64 + j] += m;
}

// ---------------- launch ----------------
extern "C" void kernel_launch(void* const* d_in, const int* in_sizes, int n_in,
                              void* d_out, int out_size)
{
    const float* user_emb   = (const float*)d_in[0];
    const float* item_emb   = (const float*)d_in[1];
    const float* group_emb  = (const float*)d_in[2];
    const float* user_hyper = (const float*)d_in[3];
    const float* item_hyper = (const float*)d_in[4];
    const float* full_hyper = (const float*)d_in[5];

    int wbase = 6;
    if (n_in >= 15 && in_sizes[6] == 1 && in_sizes[7] == 1) wbase = 8;
    const float* qc_w1  = (const float*)d_in[wbase + 0];
    const float* qc_b1  = (const float*)d_in[wbase + 1];
    const float* qc_w2  = (const float*)d_in[wbase + 2];
    const float* user_w = (const float*)d_in[wbase + 3];
    const float* user_b = (const float*)d_in[wbase + 4];
    const float* item_w = (const float*)d_in[wbase + 5];
    const float* item_b = (const float*)d_in[wbase + 6];

    float* out = (float*)d_out;

    float *cur, *mu, *mi, *mg;
    cudaGetSymbolAddress((void**)&cur, g_cur);
    cudaGetSymbolAddress((void**)&mu,  g_msgu);
    cudaGetSymbolAddress((void**)&mi,  g_msgi);
    cudaGetSymbolAddress((void**)&mg,  g_msg);

    init_kernel<<<(N_TOT * EMBD + 255) / 256, 256>>>(user_emb, item_emb, group_emb, out, cur);

    const int KC_U = 1280;   // 24 splits over K=30000
    const int KC_I = 2560;   // 24 splits over K=60000

    for (int l = 0; l < 2; l++) {
        zero_msgs<<<(G_CNT * EMBD + 255) / 256, 256>>>(mu, mi);

        // msg_u = user_hyper @ cur[:U]
        {
            dim3 grid((G_CNT + 127) / 128, (U_CNT + KC_U - 1) / KC_U);
            gemm_n64<true><<<grid, 256>>>(user_hyper, cur, mu, nullptr,
                                          G_CNT, U_CNT, KC_U);
        }
        // msg_i = item_hyper @ cur[U:]
        {
            dim3 grid((G_CNT + 127) / 128, (I_CNT + KC_I - 1) / KC_I);
            gemm_n64<true><<<grid, 256>>>(item_hyper, cur + (size_t)U_CNT * EMBD, mi, nullptr,
                                          G_CNT, I_CNT, KC_I);
        }
        // attention + MLPs -> msg ; out_he += msg
        group_kernel<<<G_CNT / 4, 256>>>(mu, mi, group_emb,
                                         qc_w1 + l * 64 * 64, qc_b1 + l * 64,
                                         qc_w2 + l * 64,
                                         user_w + l * 128 * 64, user_b + l * 64,
                                         item_w + l * 128 * 64, item_b + l * 64,
                                         mg, out);
        // cur = full_hyper @ msg ; out[:90000*64] += cur
        {
            dim3 grid((N_UI + 127) / 128, 1);
            gemm_n64<false><<<grid, 256>>>(full_hyper, mg, cur, out,
                                           N_UI, G_CNT, G_CNT);
        }
    }
    (void)in_sizes; (void)n_in; (void)out_size;
}

// round 5
// speedup vs baseline: 3.5697x; 2.5448x over previous
#include <cuda_runtime.h>
#include <cuda_bf16.h>
#include <stdint.h>
#include <math.h>

#define U_CNT 30000
#define I_CNT 60000
#define G_CNT 2000
#define N_UI  90000
#define N_TOT 92000

// ---------------- device scratch (static, no allocation) ----------------
__device__ __nv_bfloat16 g_curh[N_UI * 64];
__device__ __nv_bfloat16 g_curl[N_UI * 64];
__device__ __nv_bfloat16 g_msgh[G_CNT * 64];
__device__ __nv_bfloat16 g_msgl[G_CNT * 64];
__device__ float g_msgu[G_CNT * 64];
__device__ float g_msgi[G_CNT * 64];

// ---------------- PTX helpers ----------------
__device__ __forceinline__ uint32_t smem_u32(const void* p) {
    uint32_t a;
    asm("{ .reg .u64 t; cvta.to.shared.u64 t, %1; cvt.u32.u64 %0, t; }" : "=r"(a) : "l"(p));
    return a;
}
// pack: low half = bf16(lo), high half = bf16(hi)
__device__ __forceinline__ uint32_t bf2(float lo, float hi) {
    uint32_t r;
    asm("cvt.rn.bf16x2.f32 %0, %1, %2;" : "=r"(r) : "f"(hi), "f"(lo));
    return r;
}
__device__ __forceinline__ void ldsm4(uint32_t* r, uint32_t addr) {
    asm volatile("ldmatrix.sync.aligned.m8n8.x4.shared.b16 {%0,%1,%2,%3}, [%4];"
                 : "=r"(r[0]), "=r"(r[1]), "=r"(r[2]), "=r"(r[3]) : "r"(addr));
}
__device__ __forceinline__ void ldsm4t(uint32_t* r, uint32_t addr) {
    asm volatile("ldmatrix.sync.aligned.m8n8.x4.trans.shared.b16 {%0,%1,%2,%3}, [%4];"
                 : "=r"(r[0]), "=r"(r[1]), "=r"(r[2]), "=r"(r[3]) : "r"(addr));
}
__device__ __forceinline__ void mma16816(float* c, const uint32_t* a, uint32_t b0, uint32_t b1) {
    asm volatile("mma.sync.aligned.m16n8k16.row.col.f32.bf16.bf16.f32 "
                 "{%0,%1,%2,%3}, {%4,%5,%6,%7}, {%8,%9}, {%0,%1,%2,%3};"
                 : "+f"(c[0]), "+f"(c[1]), "+f"(c[2]), "+f"(c[3])
                 : "r"(a[0]), "r"(a[1]), "r"(a[2]), "r"(a[3]), "r"(b0), "r"(b1));
}

// ---------------- smem layout (bytes), row stride 144B (64+8 bf16) ----------------
#define O_AH   0u
#define O_AL   18432u
#define O_BH   36864u
#define O_BL   46080u
#define BUFB   55296u
#define SM_TOT (2u * BUFB)

// ---------------- fused GEMM:  C[M,64] = A[M,K](f32) @ B[K,64] ----------------
// A converted inline to bf16 hi/lo; B provided as bf16 hi/lo planes [K][64].
// 3-term split MMA: AhBh + AlBh + AhBl, f32 accum.
template <bool ATOMIC>
__global__ void __launch_bounds__(512)
gemm_mma(const float* __restrict__ A,
         const __nv_bfloat16* __restrict__ Bh_g, const __nv_bfloat16* __restrict__ Bl_g,
         float* __restrict__ Cacc, float* __restrict__ outAdd,
         __nv_bfloat16* __restrict__ Th, __nv_bfloat16* __restrict__ Tl,
         int M, int K, int kChunk)
{
    extern __shared__ char sm[];
    const uint32_t sb = smem_u32(sm);
    const int tid  = threadIdx.x;
    const int lane = tid & 31;
    const int wid  = tid >> 5;
    const int wy   = wid & 3;        // m-quadrant (32 rows)
    const int wx   = wid >> 2;       // n-quadrant (16 cols)

    const int m0   = blockIdx.x << 7;
    const int k0   = blockIdx.y * kChunk;
    const int kEnd = min(k0 + kChunk, K);
    const int nb   = (kEnd - k0 + 63) >> 6;

    // fragment smem offsets (per lane)
    const int li = lane >> 3, lr = lane & 7;
    const uint32_t aoff = (uint32_t)((wy * 32 + (li & 1) * 8 + lr) * 144 + (li >> 1) * 16);
    const uint32_t boff = (uint32_t)(((li & 1) * 8 + lr) * 144 + wx * 32 + (li >> 1) * 16);

    // A loader mapping: row = tid>>2 (0..127), 4 float4-chunks
    const int ar = tid >> 2, ac = tid & 3;
    const float* Arow = A + (size_t)(m0 + ar) * K;
    const bool amok = (m0 + ar) < M;
    // B loader mapping: row k = tid>>3 (0..63), chunk = tid&7 (16B)
    const int br = tid >> 3, bc = tid & 7;

    float acc[2][2][4];
#pragma unroll
    for (int i = 0; i < 2; i++)
#pragma unroll
        for (int j = 0; j < 2; j++)
#pragma unroll
            for (int q = 0; q < 4; q++) acc[i][j][q] = 0.f;

    // ---- build buffer 0 (monolithic)
    {
        const int kb = k0;
#pragma unroll
        for (int q = 0; q < 4; q++) {
            const int kk = (ac + 4 * q) * 4;
            float4 v = make_float4(0.f, 0.f, 0.f, 0.f);
            if (amok) {
                if (kb + kk + 3 < kEnd) v = *(const float4*)(Arow + kb + kk);
                else { float* pv = (float*)&v;
                    for (int t = 0; t < 4; t++) if (kb + kk + t < kEnd) pv[t] = Arow[kb + kk + t]; }
            }
            const uint32_t h01 = bf2(v.x, v.y), h23 = bf2(v.z, v.w);
            const float hx = __uint_as_float(h01 << 16), hy = __uint_as_float(h01 & 0xFFFF0000u);
            const float hz = __uint_as_float(h23 << 16), hw = __uint_as_float(h23 & 0xFFFF0000u);
            char* p = sm + O_AH + ar * 144 + kk * 2;
            *(uint2*)p = make_uint2(h01, h23);
            *(uint2*)(p + (O_AL - O_AH)) = make_uint2(bf2(v.x - hx, v.y - hy), bf2(v.z - hz, v.w - hw));
        }
        const int kg = kb + br;
        uint4 vh = make_uint4(0,0,0,0), vl = make_uint4(0,0,0,0);
        if (kg < kEnd) {
            vh = *(const uint4*)(Bh_g + (size_t)kg * 64 + bc * 8);
            vl = *(const uint4*)(Bl_g + (size_t)kg * 64 + bc * 8);
        }
        *(uint4*)(sm + O_BH + br * 144 + bc * 16) = vh;
        *(uint4*)(sm + O_BL + br * 144 + bc * 16) = vl;
    }
    __syncthreads();

    for (int b = 0; b < nb; b++) {
        const uint32_t bo  = (uint32_t)(b & 1) * BUFB;
        const uint32_t nbo = BUFB - bo;

        // ---- prefetch next K-block into registers (LDGs issued before MMAs)
        float4 av[4];
        uint4 bvh, bvl;
        const bool more = (b + 1 < nb);
        if (more) {
            const int kb = k0 + ((b + 1) << 6);
#pragma unroll
            for (int q = 0; q < 4; q++) {
                const int kk = (ac + 4 * q) * 4;
                float4 v = make_float4(0.f, 0.f, 0.f, 0.f);
                if (amok) {
                    if (kb + kk + 3 < kEnd) v = *(const float4*)(Arow + kb + kk);
                    else { float* pv = (float*)&v;
                        for (int t = 0; t < 4; t++) if (kb + kk + t < kEnd) pv[t] = Arow[kb + kk + t]; }
                }
                av[q] = v;
            }
            const int kg = kb + br;
            bvh = make_uint4(0,0,0,0); bvl = make_uint4(0,0,0,0);
            if (kg < kEnd) {
                bvh = *(const uint4*)(Bh_g + (size_t)kg * 64 + bc * 8);
                bvl = *(const uint4*)(Bl_g + (size_t)kg * 64 + bc * 8);
            }
        }

        // ---- MMA over this buffer (4 k-steps of 16)
#pragma unroll
        for (int ks = 0; ks < 4; ks++) {
            uint32_t ah[8], al[8], bh[4], bl[4];
            const uint32_t ka = aoff + ks * 32;
            ldsm4(ah,     sb + bo + O_AH + ka);
            ldsm4(ah + 4, sb + bo + O_AH + ka + 2304u);   // mt=1: +16 rows * 144
            ldsm4(al,     sb + bo + O_AL + ka);
            ldsm4(al + 4, sb + bo + O_AL + ka + 2304u);
            const uint32_t kbb = boff + ks * 2304u;       // +16 k-rows * 144
            ldsm4t(bh, sb + bo + O_BH + kbb);
            ldsm4t(bl, sb + bo + O_BL + kbb);
#pragma unroll
            for (int mt = 0; mt < 2; mt++)
#pragma unroll
                for (int nt = 0; nt < 2; nt++) {
                    mma16816(acc[mt][nt], ah + 4 * mt, bh[2 * nt], bh[2 * nt + 1]);
                    mma16816(acc[mt][nt], al + 4 * mt, bh[2 * nt], bh[2 * nt + 1]);
                    mma16816(acc[mt][nt], ah + 4 * mt, bl[2 * nt], bl[2 * nt + 1]);
                }
        }

        // ---- convert + store prefetched data into the other buffer
        if (more) {
#pragma unroll
            for (int q = 0; q < 4; q++) {
                const int kk = (ac + 4 * q) * 4;
                const float4 v = av[q];
                const uint32_t h01 = bf2(v.x, v.y), h23 = bf2(v.z, v.w);
                const float hx = __uint_as_float(h01 << 16), hy = __uint_as_float(h01 & 0xFFFF0000u);
                const float hz = __uint_as_float(h23 << 16), hw = __uint_as_float(h23 & 0xFFFF0000u);
                char* p = sm + nbo + O_AH + ar * 144 + kk * 2;
                *(uint2*)p = make_uint2(h01, h23);
                *(uint2*)(p + (O_AL - O_AH)) = make_uint2(bf2(v.x - hx, v.y - hy), bf2(v.z - hz, v.w - hw));
            }
            *(uint4*)(sm + nbo + O_BH + br * 144 + bc * 16) = bvh;
            *(uint4*)(sm + nbo + O_BL + br * 144 + bc * 16) = bvl;
        }
        __syncthreads();
    }

    // ---- epilogue
#pragma unroll
    for (int mt = 0; mt < 2; mt++) {
        const int rbase = m0 + wy * 32 + mt * 16 + (lane >> 2);
#pragma unroll
        for (int nt = 0; nt < 2; nt++) {
            const int j = wx * 16 + nt * 8 + (lane & 3) * 2;
            const float* c = acc[mt][nt];
#pragma unroll
            for (int half = 0; half < 2; half++) {
                const int r = rbase + half * 8;
                if (r < M) {
                    const int idx = r * 64 + j;
                    const float v0 = c[half * 2], v1 = c[half * 2 + 1];
                    if (ATOMIC) {
                        atomicAdd(&Cacc[idx], v0);
                        atomicAdd(&Cacc[idx + 1], v1);
                    } else {
                        float2 o = *(float2*)&outAdd[idx];
                        o.x += v0; o.y += v1;
                        *(float2*)&outAdd[idx] = o;
                        if (Th) {
                            const uint32_t h = bf2(v0, v1);
                            const float h0 = __uint_as_float(h << 16), h1 = __uint_as_float(h & 0xFFFF0000u);
                            *(uint32_t*)(Th + idx) = h;
                            *(uint32_t*)(Tl + idx) = bf2(v0 - h0, v1 - h1);
                        }
                    }
                }
            }
        }
    }
}

// ---------------- init: out = [ue;ie;ge]; cur planes from embeddings ----------------
__global__ void init_all(const float* __restrict__ ue, const float* __restrict__ ie,
                         const float* __restrict__ ge, float* __restrict__ out,
                         __nv_bfloat16* __restrict__ ch, __nv_bfloat16* __restrict__ cl)
{
    int i = blockIdx.x * blockDim.x + threadIdx.x;
    const int t = N_UI * 64;
    if (i < t) {
        const float v = (i < U_CNT * 64) ? ue[i] : ie[i - U_CNT * 64];
        out[i] = v;
        const __nv_bfloat16 h = __float2bfloat16(v);
        ch[i] = h;
        cl[i] = __float2bfloat16(v - __bfloat162float(h));
    } else if (i < t + G_CNT * 64) {
        out[i] = ge[i - t];
    }
}

__global__ void zero_msgs(float* __restrict__ mu, float* __restrict__ mi)
{
    int i = blockIdx.x * blockDim.x + threadIdx.x;
    if (i < G_CNT * 64) { mu[i] = 0.f; mi[i] = 0.f; }
}

// ---------------- per-group attention + MLP fusion ----------------
__global__ void __launch_bounds__(256)
group_kernel(const float* __restrict__ mu, const float* __restrict__ mi,
             const float* __restrict__ gemb,
             const float* __restrict__ qc_w1, const float* __restrict__ qc_b1,
             const float* __restrict__ qc_w2,
             const float* __restrict__ user_w, const float* __restrict__ user_b,
             const float* __restrict__ item_w, const float* __restrict__ item_b,
             __nv_bfloat16* __restrict__ mh, __nv_bfloat16* __restrict__ ml,
             float* __restrict__ out)
{
    const int sub = threadIdx.x >> 6, j = threadIdx.x & 63;
    const int g = blockIdx.x * 4 + sub;
    __shared__ float xu[4][64], xi[4][64], ge[4][64], du[4][64], di[4][64], rA[4][64], rB[4][64];

    xu[sub][j] = mu[g * 64 + j];
    xi[sub][j] = mi[g * 64 + j];
    ge[sub][j] = gemb[g * 64 + j];
    __syncthreads();
    {
        float hu = qc_b1[j], hi = qc_b1[j];
#pragma unroll 8
        for (int k = 0; k < 64; k++) {
            const float w = qc_w1[k * 64 + j];
            hu = fmaf(xu[sub][k], w, hu);
            hi = fmaf(xi[sub][k], w, hi);
        }
        const float w2 = qc_w2[j];
        rA[sub][j] = tanhf(hu) * w2;
        rB[sub][j] = tanhf(hi) * w2;
    }
    __syncthreads();
    for (int s = 32; s > 0; s >>= 1) {
        if (j < s) { rA[sub][j] += rA[sub][j + s]; rB[sub][j] += rB[sub][j + s]; }
        __syncthreads();
    }
    const float qu = rA[sub][0], qi = rB[sub][0];
    const float mx = fmaxf(qu, qi);
    const float eu = expf(qu - mx), ei = expf(qi - mx);
    const float w0 = eu / (eu + ei), w1 = ei / (eu + ei);
    const float c = w0 * xu[sub][j] + w1 * xi[sub][j];
    du[sub][j] = xu[sub][j] - c;
    di[sub][j] = xi[sub][j] - c;
    __syncthreads();

    float u2 = user_b[j], i2 = item_b[j];
#pragma unroll 8
    for (int k = 0; k < 64; k++) {
        u2 = fmaf(du[sub][k], user_w[k * 64 + j], u2);
        i2 = fmaf(di[sub][k], item_w[k * 64 + j], i2);
    }
#pragma unroll 8
    for (int k = 0; k < 64; k++) {
        const float gv = ge[sub][k];
        u2 = fmaf(gv, user_w[(64 + k) * 64 + j], u2);
        i2 = fmaf(gv, item_w[(64 + k) * 64 + j], i2);
    }
    const float m = u2 + i2 + c;
    out[N_UI * 64 + g * 64 + j] += m;
    const __nv_bfloat16 h = __float2bfloat16(m);
    mh[g * 64 + j] = h;
    ml[g * 64 + j] = __float2bfloat16(m - __bfloat162float(h));
}

// ---------------- launch ----------------
extern "C" void kernel_launch(void* const* d_in, const int* in_sizes, int n_in,
                              void* d_out, int out_size)
{
    const float* user_emb   = (const float*)d_in[0];
    const float* item_emb   = (const float*)d_in[1];
    const float* group_emb  = (const float*)d_in[2];
    const float* user_hyper = (const float*)d_in[3];
    const float* item_hyper = (const float*)d_in[4];
    const float* full_hyper = (const float*)d_in[5];
    int wbase = 6;
    if (n_in >= 15 && in_sizes[6] == 1 && in_sizes[7] == 1) wbase = 8;
    const float* qc_w1  = (const float*)d_in[wbase + 0];
    const float* qc_b1  = (const float*)d_in[wbase + 1];
    const float* qc_w2  = (const float*)d_in[wbase + 2];
    const float* user_w = (const float*)d_in[wbase + 3];
    const float* user_b = (const float*)d_in[wbase + 4];
    const float* item_w = (const float*)d_in[wbase + 5];
    const float* item_b = (const float*)d_in[wbase + 6];
    float* out = (float*)d_out;

    __nv_bfloat16 *ch, *cl, *mh, *ml;
    float *mu, *mi;
    cudaGetSymbolAddress((void**)&ch, g_curh);
    cudaGetSymbolAddress((void**)&cl, g_curl);
    cudaGetSymbolAddress((void**)&mh, g_msgh);
    cudaGetSymbolAddress((void**)&ml, g_msgl);
    cudaGetSymbolAddress((void**)&mu, g_msgu);
    cudaGetSymbolAddress((void**)&mi, g_msgi);

    cudaFuncSetAttribute(gemm_mma<true>,  cudaFuncAttributeMaxDynamicSharedMemorySize, SM_TOT);
    cudaFuncSetAttribute(gemm_mma<false>, cudaFuncAttributeMaxDynamicSharedMemorySize, SM_TOT);

    init_all<<<(N_TOT * 64 + 255) / 256, 256>>>(user_emb, item_emb, group_emb, out, ch, cl);

    for (int l = 0; l < 2; l++) {
        zero_msgs<<<(G_CNT * 64 + 255) / 256, 256>>>(mu, mi);

        // msg_u = user_hyper @ cur[:U]      (split-K, atomics)
        gemm_mma<true><<<dim3(16, 16), 512, SM_TOT>>>(
            user_hyper, ch, cl, mu, nullptr, nullptr, nullptr, G_CNT, U_CNT, 1920);
        // msg_i = item_hyper @ cur[U:]
        gemm_mma<true><<<dim3(16, 16), 512, SM_TOT>>>(
            item_hyper, ch + (size_t)U_CNT * 64, cl + (size_t)U_CNT * 64,
            mi, nullptr, nullptr, nullptr, G_CNT, I_CNT, 3840);
        // attention + MLPs -> msg planes ; out_he += msg
        group_kernel<<<G_CNT / 4, 256>>>(mu, mi, group_emb,
            qc_w1 + l * 64 * 64, qc_b1 + l * 64, qc_w2 + l * 64,
            user_w + l * 128 * 64, user_b + l * 64,
            item_w + l * 128 * 64, item_b + l * 64, mh, ml, out);
        // node_emb = full_hyper @ msg ; out += ; cur planes for next layer (layer 0 only)
        gemm_mma<false><<<dim3(704, 1), 512, SM_TOT>>>(
            full_hyper, mh, ml, nullptr, out,
            (l == 0) ? ch : nullptr, (l == 0) ? cl : nullptr, N_UI, G_CNT, 2048);
    }
    (void)in_sizes; (void)n_in; (void)out_size;
}

// round 6
// speedup vs baseline: 3.6972x; 1.0357x over previous
#include <cuda_runtime.h>
#include <cuda_bf16.h>
#include <stdint.h>
#include <math.h>

#define U_CNT 30000
#define I_CNT 60000
#define G_CNT 2000
#define N_UI  90000
#define N_TOT 92000

// ---------------- device scratch (static, no allocation) ----------------
__device__ __nv_bfloat16 g_curh[N_UI * 64];
__device__ __nv_bfloat16 g_curl[N_UI * 64];
__device__ __nv_bfloat16 g_msgh[G_CNT * 64];
__device__ __nv_bfloat16 g_msgl[G_CNT * 64];
__device__ float g_msgu[G_CNT * 64];
__device__ float g_msgi[G_CNT * 64];

// ---------------- PTX helpers ----------------
__device__ __forceinline__ uint32_t smem_u32(const void* p) {
    uint32_t a;
    asm("{ .reg .u64 t; cvta.to.shared.u64 t, %1; cvt.u32.u64 %0, t; }" : "=r"(a) : "l"(p));
    return a;
}
__device__ __forceinline__ uint32_t bf2(float lo, float hi) {  // low=bf16(lo), high=bf16(hi)
    uint32_t r;
    asm("cvt.rn.bf16x2.f32 %0, %1, %2;" : "=r"(r) : "f"(hi), "f"(lo));
    return r;
}
__device__ __forceinline__ void ldsm4(uint32_t* r, uint32_t addr) {
    asm volatile("ldmatrix.sync.aligned.m8n8.x4.shared.b16 {%0,%1,%2,%3}, [%4];"
                 : "=r"(r[0]), "=r"(r[1]), "=r"(r[2]), "=r"(r[3]) : "r"(addr));
}
__device__ __forceinline__ void ldsm4t(uint32_t* r, uint32_t addr) {
    asm volatile("ldmatrix.sync.aligned.m8n8.x4.trans.shared.b16 {%0,%1,%2,%3}, [%4];"
                 : "=r"(r[0]), "=r"(r[1]), "=r"(r[2]), "=r"(r[3]) : "r"(addr));
}
__device__ __forceinline__ void mma16816(float* c, const uint32_t* a, uint32_t b0, uint32_t b1) {
    asm volatile("mma.sync.aligned.m16n8k16.row.col.f32.bf16.bf16.f32 "
                 "{%0,%1,%2,%3}, {%4,%5,%6,%7}, {%8,%9}, {%0,%1,%2,%3};"
                 : "+f"(c[0]), "+f"(c[1]), "+f"(c[2]), "+f"(c[3])
                 : "r"(a[0]), "r"(a[1]), "r"(a[2]), "r"(a[3]), "r"(b0), "r"(b1));
}
__device__ __forceinline__ void cpasync16(uint32_t dst, const void* src, uint32_t sz) {
    asm volatile("cp.async.ca.shared.global [%0], [%1], 16, %2;"
                 :: "r"(dst), "l"(src), "r"(sz) : "memory");
}
__device__ __forceinline__ void cpasync_commit() {
    asm volatile("cp.async.commit_group;" ::: "memory");
}
__device__ __forceinline__ void cpasync_wait0() {
    asm volatile("cp.async.wait_group 0;" ::: "memory");
}

// ---------------- smem layout: swizzled 128B rows ----------------
#define O_AH   0u
#define O_AL   16384u
#define O_BH   32768u
#define O_BL   40960u
#define BUFB   49152u
#define SM_TOT 98304

// ---------------- fused GEMM:  C[M,64] = A[M,K](f32) @ B[K,64] ----------------
// A converted inline to bf16 hi/lo; B provided as bf16 hi/lo planes [K][64].
// 3-term split MMA with 3 independent accumulator sets.
template <bool ATOMIC>
__global__ void __launch_bounds__(512)
gemm_mma(const float* __restrict__ A,
         const __nv_bfloat16* __restrict__ Bh_g, const __nv_bfloat16* __restrict__ Bl_g,
         float* __restrict__ Cacc, float* __restrict__ outAdd,
         __nv_bfloat16* __restrict__ Th, __nv_bfloat16* __restrict__ Tl,
         int M, int K, int kChunk)
{
    extern __shared__ char sm[];
    const uint32_t sb = smem_u32(sm);
    const int tid  = threadIdx.x;
    const int lane = tid & 31;
    const int wid  = tid >> 5;
    const int wy   = wid & 3;        // m-quadrant (32 rows)
    const int wx   = wid >> 2;       // n-quadrant (16 cols)

    const int m0   = blockIdx.x << 7;
    const int k0   = blockIdx.y * kChunk;
    const int kEnd = min(k0 + kChunk, K);
    const int nb   = (kEnd - k0 + 63) >> 6;

    // fragment addressing (swizzled)
    const int li = lane >> 3, lr = lane & 7;
    const int chi = li >> 1, rsel = li & 1;
    const uint32_t ra0 = (uint32_t)((wy * 32 + rsel * 8 + lr) * 128);   // A mt=0 row base
    const uint32_t ra1 = ra0 + 16u * 128u;                               // A mt=1
    const uint32_t bconst = (uint32_t)((rsel * 8 + lr) * 128 + (((wx * 2 + chi) ^ lr) << 4));

    // A loader: row = tid>>2 (0..127), ac = tid&3 → float4 k-chunks ac+4q
    const int ar = tid >> 2, ac = tid & 3;
    const float* Arow = A + (size_t)(m0 + ar) * K;
    const bool amok = (m0 + ar) < M;
    const uint32_t ar7 = (uint32_t)(ar & 7);

    // B loader (cp.async): kr = tid>>3 (0..63), bc16 = tid&7
    const int kr = tid >> 3, bc16 = tid & 7;
    const uint32_t bdst = (uint32_t)(kr * 128 + (((bc16 ^ (kr & 7))) << 4));

    float accA[2][2][4], accB[2][2][4], accC[2][2][4];
#pragma unroll
    for (int i = 0; i < 2; i++)
#pragma unroll
        for (int j = 0; j < 2; j++)
#pragma unroll
            for (int q = 0; q < 4; q++) { accA[i][j][q] = 0.f; accB[i][j][q] = 0.f; accC[i][j][q] = 0.f; }

    // ---- helper lambdas (inlined) for A convert-store and B cp.async
    auto storeA = [&](uint32_t bufo, const float4* av) {
#pragma unroll
        for (int q = 0; q < 4; q++) {
            const int k4 = ac + 4 * q;          // float4 index along k (0..15)
            const float4 v = av[q];
            const uint32_t h01 = bf2(v.x, v.y), h23 = bf2(v.z, v.w);
            const float hx = __uint_as_float(h01 << 16), hy = __uint_as_float(h01 & 0xFFFF0000u);
            const float hz = __uint_as_float(h23 << 16), hw = __uint_as_float(h23 & 0xFFFF0000u);
            const uint32_t c16 = (uint32_t)(k4 >> 1);
            const uint32_t sub8 = (uint32_t)((k4 & 1) << 3);
            const uint32_t off = (uint32_t)(ar * 128) + (((c16 ^ ar7)) << 4) + sub8;
            *(uint2*)(sm + bufo + O_AH + off) = make_uint2(h01, h23);
            *(uint2*)(sm + bufo + O_AL + off) = make_uint2(bf2(v.x - hx, v.y - hy), bf2(v.z - hz, v.w - hw));
        }
    };
    auto loadAreg = [&](int kb, float4* av) {
#pragma unroll
        for (int q = 0; q < 4; q++) {
            const int kk = (ac + 4 * q) * 4;
            float4 v = make_float4(0.f, 0.f, 0.f, 0.f);
            if (amok) {
                if (kb + kk + 3 < kEnd) v = *(const float4*)(Arow + kb + kk);
                else { float* pv = (float*)&v;
                    for (int t = 0; t < 4; t++) if (kb + kk + t < kEnd) pv[t] = Arow[kb + kk + t]; }
            }
            av[q] = v;
        }
    };
    auto issueB = [&](uint32_t bufo, int kb) {
        const int kg = kb + kr;
        const uint32_t sz = (kg < kEnd) ? 16u : 0u;
        cpasync16(sb + bufo + O_BH + bdst, Bh_g + (size_t)kg * 64 + bc16 * 8, sz);
        cpasync16(sb + bufo + O_BL + bdst, Bl_g + (size_t)kg * 64 + bc16 * 8, sz);
    };

    // ---- fill buffer 0
    {
        float4 av[4];
        loadAreg(k0, av);
        issueB(0u, k0);
        cpasync_commit();
        storeA(0u, av);
        cpasync_wait0();
    }
    __syncthreads();

    for (int b = 0; b < nb; b++) {
        const uint32_t bo  = (uint32_t)(b & 1) * BUFB;
        const uint32_t nbo = BUFB - bo;
        const bool more = (b + 1 < nb);

        float4 av[4];
        if (more) {
            const int kb = k0 + ((b + 1) << 6);
            loadAreg(kb, av);           // LDGs in flight during MMA
            issueB(nbo, kb);
            cpasync_commit();
        }

        // ---- MMA over this buffer (4 k-steps of 16)
#pragma unroll
        for (int ks = 0; ks < 4; ks++) {
            uint32_t ah[8], al[8], bh[4], bl[4];
            const uint32_t asw = (uint32_t)(((ks * 2 + chi) ^ lr) << 4);
            ldsm4(ah,     sb + bo + O_AH + ra0 + asw);
            ldsm4(ah + 4, sb + bo + O_AH + ra1 + asw);
            ldsm4(al,     sb + bo + O_AL + ra0 + asw);
            ldsm4(al + 4, sb + bo + O_AL + ra1 + asw);
            const uint32_t bad = sb + bo + bconst + (uint32_t)(ks * 2048);
            ldsm4t(bh, bad + O_BH);
            ldsm4t(bl, bad + O_BL);
            // 12 independent MMAs (3 accumulator sets x 4 tiles)
#pragma unroll
            for (int mt = 0; mt < 2; mt++)
#pragma unroll
                for (int nt = 0; nt < 2; nt++)
                    mma16816(accA[mt][nt], ah + 4 * mt, bh[2 * nt], bh[2 * nt + 1]);
#pragma unroll
            for (int mt = 0; mt < 2; mt++)
#pragma unroll
                for (int nt = 0; nt < 2; nt++)
                    mma16816(accB[mt][nt], al + 4 * mt, bh[2 * nt], bh[2 * nt + 1]);
#pragma unroll
            for (int mt = 0; mt < 2; mt++)
#pragma unroll
                for (int nt = 0; nt < 2; nt++)
                    mma16816(accC[mt][nt], ah + 4 * mt, bl[2 * nt], bl[2 * nt + 1]);
        }

        if (more) {
            storeA(nbo, av);
            cpasync_wait0();
        }
        __syncthreads();
    }

    // ---- epilogue
#pragma unroll
    for (int mt = 0; mt < 2; mt++) {
        const int rbase = m0 + wy * 32 + mt * 16 + (lane >> 2);
#pragma unroll
        for (int nt = 0; nt < 2; nt++) {
            const int j = wx * 16 + nt * 8 + (lane & 3) * 2;
#pragma unroll
            for (int half = 0; half < 2; half++) {
                const int r = rbase + half * 8;
                if (r < M) {
                    const int idx = r * 64 + j;
                    const float v0 = accA[mt][nt][half * 2]     + accB[mt][nt][half * 2]     + accC[mt][nt][half * 2];
                    const float v1 = accA[mt][nt][half * 2 + 1] + accB[mt][nt][half * 2 + 1] + accC[mt][nt][half * 2 + 1];
                    if (ATOMIC) {
                        atomicAdd(&Cacc[idx], v0);
                        atomicAdd(&Cacc[idx + 1], v1);
                    } else {
                        float2 o = *(float2*)&outAdd[idx];
                        o.x += v0; o.y += v1;
                        *(float2*)&outAdd[idx] = o;
                        if (Th) {
                            const uint32_t h = bf2(v0, v1);
                            const float h0 = __uint_as_float(h << 16), h1 = __uint_as_float(h & 0xFFFF0000u);
                            *(uint32_t*)(Th + idx) = h;
                            *(uint32_t*)(Tl + idx) = bf2(v0 - h0, v1 - h1);
                        }
                    }
                }
            }
        }
    }
}

// ---------------- init: out = [ue;ie;ge]; cur planes from embeddings ----------------
__global__ void init_all(const float* __restrict__ ue, const float* __restrict__ ie,
                         const float* __restrict__ ge, float* __restrict__ out,
                         __nv_bfloat16* __restrict__ ch, __nv_bfloat16* __restrict__ cl)
{
    int i = blockIdx.x * blockDim.x + threadIdx.x;
    const int t = N_UI * 64;
    if (i < t) {
        const float v = (i < U_CNT * 64) ? ue[i] : ie[i - U_CNT * 64];
        out[i] = v;
        const __nv_bfloat16 h = __float2bfloat16(v);
        ch[i] = h;
        cl[i] = __float2bfloat16(v - __bfloat162float(h));
    } else if (i < t + G_CNT * 64) {
        out[i] = ge[i - t];
    }
}

__global__ void zero_msgs(float* __restrict__ mu, float* __restrict__ mi)
{
    int i = blockIdx.x * blockDim.x + threadIdx.x;
    if (i < G_CNT * 64) { mu[i] = 0.f; mi[i] = 0.f; }
}

// ---------------- per-group attention + MLP fusion ----------------
__global__ void __launch_bounds__(256)
group_kernel(const float* __restrict__ mu, const float* __restrict__ mi,
             const float* __restrict__ gemb,
             const float* __restrict__ qc_w1, const float* __restrict__ qc_b1,
             const float* __restrict__ qc_w2,
             const float* __restrict__ user_w, const float* __restrict__ user_b,
             const float* __restrict__ item_w, const float* __restrict__ item_b,
             __nv_bfloat16* __restrict__ mh, __nv_bfloat16* __restrict__ ml,
             float* __restrict__ out)
{
    const int sub = threadIdx.x >> 6, j = threadIdx.x & 63;
    const int g = blockIdx.x * 4 + sub;
    __shared__ float xu[4][64], xi[4][64], ge[4][64], du[4][64], di[4][64], rA[4][64], rB[4][64];

    xu[sub][j] = mu[g * 64 + j];
    xi[sub][j] = mi[g * 64 + j];
    ge[sub][j] = gemb[g * 64 + j];
    __syncthreads();
    {
        float hu = qc_b1[j], hi = qc_b1[j];
#pragma unroll 8
        for (int k = 0; k < 64; k++) {
            const float w = qc_w1[k * 64 + j];
            hu = fmaf(xu[sub][k], w, hu);
            hi = fmaf(xi[sub][k], w, hi);
        }
        const float w2 = qc_w2[j];
        rA[sub][j] = tanhf(hu) * w2;
        rB[sub][j] = tanhf(hi) * w2;
    }
    __syncthreads();
    for (int s = 32; s > 0; s >>= 1) {
        if (j < s) { rA[sub][j] += rA[sub][j + s]; rB[sub][j] += rB[sub][j + s]; }
        __syncthreads();
    }
    const float qu = rA[sub][0], qi = rB[sub][0];
    const float mx = fmaxf(qu, qi);
    const float eu = expf(qu - mx), ei = expf(qi - mx);
    const float w0 = eu / (eu + ei), w1 = ei / (eu + ei);
    const float c = w0 * xu[sub][j] + w1 * xi[sub][j];
    du[sub][j] = xu[sub][j] - c;
    di[sub][j] = xi[sub][j] - c;
    __syncthreads();

    float u2 = user_b[j], i2 = item_b[j];
#pragma unroll 8
    for (int k = 0; k < 64; k++) {
        u2 = fmaf(du[sub][k], user_w[k * 64 + j], u2);
        i2 = fmaf(di[sub][k], item_w[k * 64 + j], i2);
    }
#pragma unroll 8
    for (int k = 0; k < 64; k++) {
        const float gv = ge[sub][k];
        u2 = fmaf(gv, user_w[(64 + k) * 64 + j], u2);
        i2 = fmaf(gv, item_w[(64 + k) * 64 + j], i2);
    }
    const float m = u2 + i2 + c;
    out[N_UI * 64 + g * 64 + j] += m;
    const __nv_bfloat16 h = __float2bfloat16(m);
    mh[g * 64 + j] = h;
    ml[g * 64 + j] = __float2bfloat16(m - __bfloat162float(h));
}

// ---------------- launch ----------------
extern "C" void kernel_launch(void* const* d_in, const int* in_sizes, int n_in,
                              void* d_out, int out_size)
{
    const float* user_emb   = (const float*)d_in[0];
    const float* item_emb   = (const float*)d_in[1];
    const float* group_emb  = (const float*)d_in[2];
    const float* user_hyper = (const float*)d_in[3];
    const float* item_hyper = (const float*)d_in[4];
    const float* full_hyper = (const float*)d_in[5];
    int wbase = 6;
    if (n_in >= 15 && in_sizes[6] == 1 && in_sizes[7] == 1) wbase = 8;
    const float* qc_w1  = (const float*)d_in[wbase + 0];
    const float* qc_b1  = (const float*)d_in[wbase + 1];
    const float* qc_w2  = (const float*)d_in[wbase + 2];
    const float* user_w = (const float*)d_in[wbase + 3];
    const float* user_b = (const float*)d_in[wbase + 4];
    const float* item_w = (const float*)d_in[wbase + 5];
    const float* item_b = (const float*)d_in[wbase + 6];
    float* out = (float*)d_out;

    __nv_bfloat16 *ch, *cl, *mh, *ml;
    float *mu, *mi;
    cudaGetSymbolAddress((void**)&ch, g_curh);
    cudaGetSymbolAddress((void**)&cl, g_curl);
    cudaGetSymbolAddress((void**)&mh, g_msgh);
    cudaGetSymbolAddress((void**)&ml, g_msgl);
    cudaGetSymbolAddress((void**)&mu, g_msgu);
    cudaGetSymbolAddress((void**)&mi, g_msgi);

    cudaFuncSetAttribute(gemm_mma<true>,  cudaFuncAttributeMaxDynamicSharedMemorySize, SM_TOT);
    cudaFuncSetAttribute(gemm_mma<false>, cudaFuncAttributeMaxDynamicSharedMemorySize, SM_TOT);

    init_all<<<(N_TOT * 64 + 255) / 256, 256>>>(user_emb, item_emb, group_emb, out, ch, cl);

    for (int l = 0; l < 2; l++) {
        zero_msgs<<<(G_CNT * 64 + 255) / 256, 256>>>(mu, mi);

        // msg_u = user_hyper @ cur[:U]      (split-K, atomics)
        gemm_mma<true><<<dim3(16, 16), 512, SM_TOT>>>(
            user_hyper, ch, cl, mu, nullptr, nullptr, nullptr, G_CNT, U_CNT, 1920);
        // msg_i = item_hyper @ cur[U:]
        gemm_mma<true><<<dim3(16, 16), 512, SM_TOT>>>(
            item_hyper, ch + (size_t)U_CNT * 64, cl + (size_t)U_CNT * 64,
            mi, nullptr, nullptr, nullptr, G_CNT, I_CNT, 3840);
        // attention + MLPs -> msg planes ; out_he += msg
        group_kernel<<<G_CNT / 4, 256>>>(mu, mi, group_emb,
            qc_w1 + l * 64 * 64, qc_b1 + l * 64, qc_w2 + l * 64,
            user_w + l * 128 * 64, user_b + l * 64,
            item_w + l * 128 * 64, item_b + l * 64, mh, ml, out);
        // node_emb = full_hyper @ msg ; out += ; cur planes for next layer (layer 0 only)
        gemm_mma<false><<<dim3(704, 1), 512, SM_TOT>>>(
            full_hyper, mh, ml, nullptr, out,
            (l == 0) ? ch : nullptr, (l == 0) ? cl : nullptr, N_UI, G_CNT, 2048);
    }
    (void)in_sizes; (void)n_in; (void)out_size;
}

// round 9
// speedup vs baseline: 4.6280x; 1.2518x over previous
#include <cuda_runtime.h>
#include <cuda_fp16.h>
#include <stdint.h>
#include <math.h>

#define U_CNT 30000
#define I_CNT 60000
#define G_CNT 2000
#define N_UI  90000
#define N_TOT 92000

// ---------------- device scratch (static, no allocation) ----------------
__device__ __half g_curh[N_UI * 64];
__device__ __half g_curl[N_UI * 64];
__device__ __half g_msgh[G_CNT * 64];
__device__ __half g_msgl[G_CNT * 64];
__device__ float  g_curf[N_UI * 64];
__device__ float  g_msgf[G_CNT * 64];
__device__ float  g_msgu[G_CNT * 64];
__device__ float  g_msgi[G_CNT * 64];
// [0]=cur absmax, [1]=cur binv, [2]=msg absmax, [3]=msg binv
__device__ float  g_scales[4];

// ---------------- PTX helpers ----------------
__device__ __forceinline__ uint32_t smem_u32(const void* p) {
    uint32_t a;
    asm("{ .reg .u64 t; cvta.to.shared.u64 t, %1; cvt.u32.u64 %0, t; }" : "=r"(a) : "l"(p));
    return a;
}
__device__ __forceinline__ uint32_t f16x2(float lo, float hi) {  // low=f16(lo), high=f16(hi)
    uint32_t r;
    asm("cvt.rn.f16x2.f32 %0, %1, %2;" : "=r"(r) : "f"(hi), "f"(lo));
    return r;
}
__device__ __forceinline__ void ldsm4(uint32_t* r, uint32_t addr) {
    asm volatile("ldmatrix.sync.aligned.m8n8.x4.shared.b16 {%0,%1,%2,%3}, [%4];"
                 : "=r"(r[0]), "=r"(r[1]), "=r"(r[2]), "=r"(r[3]) : "r"(addr));
}
__device__ __forceinline__ void ldsm4t(uint32_t* r, uint32_t addr) {
    asm volatile("ldmatrix.sync.aligned.m8n8.x4.trans.shared.b16 {%0,%1,%2,%3}, [%4];"
                 : "=r"(r[0]), "=r"(r[1]), "=r"(r[2]), "=r"(r[3]) : "r"(addr));
}
__device__ __forceinline__ void mma16816(float* c, const uint32_t* a, uint32_t b0, uint32_t b1) {
    asm volatile("mma.sync.aligned.m16n8k16.row.col.f32.f16.f16.f32 "
                 "{%0,%1,%2,%3}, {%4,%5,%6,%7}, {%8,%9}, {%0,%1,%2,%3};"
                 : "+f"(c[0]), "+f"(c[1]), "+f"(c[2]), "+f"(c[3])
                 : "r"(a[0]), "r"(a[1]), "r"(a[2]), "r"(a[3]), "r"(b0), "r"(b1));
}
__device__ __forceinline__ void cpasync16(uint32_t dst, const void* src, uint32_t sz) {
    asm volatile("cp.async.ca.shared.global [%0], [%1], 16, %2;"
                 :: "r"(dst), "l"(src), "r"(sz) : "memory");
}
__device__ __forceinline__ void cpasync_commit() {
    asm volatile("cp.async.commit_group;" ::: "memory");
}
__device__ __forceinline__ void cpasync_wait0() {
    asm volatile("cp.async.wait_group 0;" ::: "memory");
}
__device__ __forceinline__ void atomic_fmax(float* addr, float v) {   // v >= 0
    atomicMax((unsigned int*)addr, __float_as_uint(v));
}

// ---------------- smem layout: swizzled 128B rows ----------------
#define O_AH   0u        // A fp16 plane: 128 x 64 x 2B = 16K
#define O_BH   16384u    // B hi plane:    64 x 64 x 2B =  8K
#define O_BL   24576u    // B lo plane:                    8K
#define BUFB   32768u
#define SM_TOT 65536

// ---------------- fused GEMM:  C[M,64] = A[M,K](f32,[0,1)) @ B[K,64] ----------------
// A -> fp16 single term; B = fp16 hi/lo planes (dynamically pre-scaled).
// C = binv * (A*Bh + A*Bl), f32 accum, 2 independent accumulator sets.
// ATOMIC: split-K atomicAdd into Cacc. else: outAdd += C, Cout = C (fp32),
// block absmax -> atomic_fmax(amax).
template <bool ATOMIC>
__global__ void __launch_bounds__(512)
gemm_mma(const float* __restrict__ A,
         const __half* __restrict__ Bh_g, const __half* __restrict__ Bl_g,
         float* __restrict__ Cacc, float* __restrict__ outAdd,
         float* __restrict__ Cout, float* __restrict__ amax,
         const float* __restrict__ binv_p,
         int M, int K, int kChunk)
{
    extern __shared__ char sm[];
    const uint32_t sb = smem_u32(sm);
    const int tid  = threadIdx.x;
    const int lane = tid & 31;
    const int wid  = tid >> 5;
    const int wy   = wid & 3;        // m-quadrant (32 rows)
    const int wx   = wid >> 2;       // n-quadrant (16 cols)

    const int m0   = blockIdx.x << 7;
    const int k0   = blockIdx.y * kChunk;
    const int kEnd = min(k0 + kChunk, K);
    const int nb   = (kEnd - k0 + 63) >> 6;

    // fragment addressing (swizzled 16B units within 128B rows)
    const int li = lane >> 3, lr = lane & 7;
    const int chi = li >> 1, rsel = li & 1;
    const uint32_t ra0 = (uint32_t)((wy * 32 + rsel * 8 + lr) * 128);
    const uint32_t ra1 = ra0 + 16u * 128u;
    const uint32_t bconst = (uint32_t)((rsel * 8 + lr) * 128 + (((wx * 2 + chi) ^ lr) << 4));

    // A loader: row = tid>>2 (0..127), ac = tid&3 -> float4 k-chunks ac+4q
    const int ar = tid >> 2, ac = tid & 3;
    const float* Arow = A + (size_t)(m0 + ar) * K;
    const bool amok = (m0 + ar) < M;
    const uint32_t ar7 = (uint32_t)(ar & 7);

    // B loader (cp.async): kr = tid>>3 (0..63), bc16 = tid&7
    const int kr = tid >> 3, bc16 = tid & 7;
    const uint32_t bdst = (uint32_t)(kr * 128 + ((bc16 ^ (kr & 7)) << 4));

    float accA[2][2][4], accB[2][2][4];
#pragma unroll
    for (int i = 0; i < 2; i++)
#pragma unroll
        for (int j = 0; j < 2; j++)
#pragma unroll
            for (int q = 0; q < 4; q++) { accA[i][j][q] = 0.f; accB[i][j][q] = 0.f; }

    auto loadAreg = [&](int kb, float4* av) {
#pragma unroll
        for (int q = 0; q < 4; q++) {
            const int kk = (ac + 4 * q) * 4;
            float4 v = make_float4(0.f, 0.f, 0.f, 0.f);
            if (amok) {
                if (kb + kk + 3 < kEnd) v = *(const float4*)(Arow + kb + kk);
                else { float* pv = (float*)&v;
                    for (int t = 0; t < 4; t++) if (kb + kk + t < kEnd) pv[t] = Arow[kb + kk + t]; }
            }
            av[q] = v;
        }
    };
    auto storeA = [&](uint32_t bufo, const float4* av) {
#pragma unroll
        for (int q = 0; q < 4; q++) {
            const int k4 = ac + 4 * q;
            const float4 v = av[q];
            const uint32_t h01 = f16x2(v.x, v.y);
            const uint32_t h23 = f16x2(v.z, v.w);
            const uint32_t c16 = (uint32_t)(k4 >> 1);
            const uint32_t sub8 = (uint32_t)((k4 & 1) << 3);
            const uint32_t off = (uint32_t)(ar * 128) + ((c16 ^ ar7) << 4) + sub8;
            *(uint2*)(sm + bufo + O_AH + off) = make_uint2(h01, h23);
        }
    };
    auto issueB = [&](uint32_t bufo, int kb) {
        const int kg = kb + kr;
        const uint32_t sz = (kg < kEnd) ? 16u : 0u;
        cpasync16(sb + bufo + O_BH + bdst, Bh_g + (size_t)kg * 64 + bc16 * 8, sz);
        cpasync16(sb + bufo + O_BL + bdst, Bl_g + (size_t)kg * 64 + bc16 * 8, sz);
    };

    // ---- fill buffer 0
    {
        float4 av[4];
        loadAreg(k0, av);
        issueB(0u, k0);
        cpasync_commit();
        storeA(0u, av);
        cpasync_wait0();
    }
    __syncthreads();

    for (int b = 0; b < nb; b++) {
        const uint32_t bo  = (uint32_t)(b & 1) * BUFB;
        const uint32_t nbo = BUFB - bo;
        const bool more = (b + 1 < nb);

        float4 av[4];
        if (more) {
            const int kb = k0 + ((b + 1) << 6);
            loadAreg(kb, av);
            issueB(nbo, kb);
            cpasync_commit();
        }

        // ---- MMA over this buffer (4 k-steps of 16)
#pragma unroll
        for (int ks = 0; ks < 4; ks++) {
            uint32_t ah[8], bh[4], bl[4];
            const uint32_t asw = (uint32_t)(((ks * 2 + chi) ^ lr) << 4);
            ldsm4(ah,     sb + bo + O_AH + ra0 + asw);
            ldsm4(ah + 4, sb + bo + O_AH + ra1 + asw);
            const uint32_t bad = sb + bo + bconst + (uint32_t)(ks * 2048);
            ldsm4t(bh, bad + O_BH);
            ldsm4t(bl, bad + O_BL);
#pragma unroll
            for (int mt = 0; mt < 2; mt++)
#pragma unroll
                for (int nt = 0; nt < 2; nt++)
                    mma16816(accA[mt][nt], ah + 4 * mt, bh[2 * nt], bh[2 * nt + 1]);
#pragma unroll
            for (int mt = 0; mt < 2; mt++)
#pragma unroll
                for (int nt = 0; nt < 2; nt++)
                    mma16816(accB[mt][nt], ah + 4 * mt, bl[2 * nt], bl[2 * nt + 1]);
        }

        if (more) {
            storeA(nbo, av);
            cpasync_wait0();
        }
        __syncthreads();
    }

    // ---- epilogue
    const float binv = *binv_p;
    float vmax = 0.f;
#pragma unroll
    for (int mt = 0; mt < 2; mt++) {
        const int rbase = m0 + wy * 32 + mt * 16 + (lane >> 2);
#pragma unroll
        for (int nt = 0; nt < 2; nt++) {
            const int j = wx * 16 + nt * 8 + (lane & 3) * 2;
#pragma unroll
            for (int half = 0; half < 2; half++) {
                const int r = rbase + half * 8;
                if (r < M) {
                    const int idx = r * 64 + j;
                    const float v0 = (accA[mt][nt][half * 2]     + accB[mt][nt][half * 2])     * binv;
                    const float v1 = (accA[mt][nt][half * 2 + 1] + accB[mt][nt][half * 2 + 1]) * binv;
                    if (ATOMIC) {
                        atomicAdd(&Cacc[idx], v0);
                        atomicAdd(&Cacc[idx + 1], v1);
                    } else {
                        float2 o = *(float2*)&outAdd[idx];
                        o.x += v0; o.y += v1;
                        *(float2*)&outAdd[idx] = o;
                        Cout[idx]     = v0;
                        Cout[idx + 1] = v1;
                        vmax = fmaxf(vmax, fmaxf(fabsf(v0), fabsf(v1)));
                    }
                }
            }
        }
    }
    if (!ATOMIC) {
        // block absmax -> global
#pragma unroll
        for (int o = 16; o > 0; o >>= 1)
            vmax = fmaxf(vmax, __shfl_xor_sync(0xFFFFFFFFu, vmax, o));
        __shared__ float wm[16];
        if (lane == 0) wm[wid] = vmax;
        __syncthreads();
        if (tid == 0) {
            float m = wm[0];
#pragma unroll
            for (int i = 1; i < 16; i++) m = fmaxf(m, wm[i]);
            atomic_fmax(amax, m);
        }
    }
}

// ---------------- conversion: fp32 tensor -> scaled fp16 hi/lo planes ----------------
__global__ void conv_plane(const float* __restrict__ X,
                           __half* __restrict__ H, __half* __restrict__ L,
                           int n, const float* __restrict__ amax_p,
                           float* __restrict__ binv_p)
{
    const float m = fmaxf(*amax_p, 1e-30f);
    int e;
    frexpf(m, &e);                              // m = f * 2^e, f in [0.5,1)
    const float s = exp2f((float)(7 - e));      // scaled max in (64,128]
    if (blockIdx.x == 0 && threadIdx.x == 0) *binv_p = exp2f((float)(e - 7));
    const int stride = gridDim.x * blockDim.x;
    for (int i = blockIdx.x * blockDim.x + threadIdx.x; i < n; i += stride) {
        const float v = X[i] * s;
        const __half h = __float2half_rn(v);
        H[i] = h;
        L[i] = __float2half_rn(v - __half2float(h));
    }
}

// ---------------- init: out = [ue;ie;ge]; curf = concat(ue,ie); absmax ----------------
__global__ void init_all(const float* __restrict__ ue, const float* __restrict__ ie,
                         const float* __restrict__ ge, float* __restrict__ out,
                         float* __restrict__ curf, float* __restrict__ amax)
{
    const int i = blockIdx.x * blockDim.x + threadIdx.x;
    const int t = N_UI * 64;
    float v = 0.f;
    if (i < t) {
        v = (i < U_CNT * 64) ? ue[i] : ie[i - U_CNT * 64];
        out[i] = v;
        curf[i] = v;
    } else if (i < t + G_CNT * 64) {
        out[i] = ge[i - t];
    }
    // block absmax of cur part
    float a = (i < t) ? fabsf(v) : 0.f;
#pragma unroll
    for (int o = 16; o > 0; o >>= 1)
        a = fmaxf(a, __shfl_xor_sync(0xFFFFFFFFu, a, o));
    __shared__ float wm[8];
    const int lane = threadIdx.x & 31, wid = threadIdx.x >> 5;
    if (lane == 0) wm[wid] = a;
    __syncthreads();
    if (threadIdx.x == 0) {
        float m = wm[0];
#pragma unroll
        for (int q = 1; q < 8; q++) m = fmaxf(m, wm[q]);
        atomic_fmax(amax, m);
    }
}

__global__ void zero_msgs(float* __restrict__ mu, float* __restrict__ mi,
                          float* __restrict__ scales)
{
    const int i = blockIdx.x * blockDim.x + threadIdx.x;
    if (i < G_CNT * 64) { mu[i] = 0.f; mi[i] = 0.f; }
    if (i == 0) { scales[0] = 0.f; scales[2] = 0.f; }
}

// ---------------- per-group attention + MLP fusion ----------------
__global__ void __launch_bounds__(256)
group_kernel(const float* __restrict__ mu, const float* __restrict__ mi,
             const float* __restrict__ gemb,
             const float* __restrict__ qc_w1, const float* __restrict__ qc_b1,
             const float* __restrict__ qc_w2,
             const float* __restrict__ user_w, const float* __restrict__ user_b,
             const float* __restrict__ item_w, const float* __restrict__ item_b,
             float* __restrict__ msgf, float* __restrict__ out,
             float* __restrict__ amax)
{
    const int sub = threadIdx.x >> 6, j = threadIdx.x & 63;
    const int g = blockIdx.x * 4 + sub;
    __shared__ float xu[4][64], xi[4][64], ge[4][64], du[4][64], di[4][64], rA[4][64], rB[4][64];

    xu[sub][j] = mu[g * 64 + j];
    xi[sub][j] = mi[g * 64 + j];
    ge[sub][j] = gemb[g * 64 + j];
    __syncthreads();
    {
        float hu = qc_b1[j], hi = qc_b1[j];
#pragma unroll 8
        for (int k = 0; k < 64; k++) {
            const float w = qc_w1[k * 64 + j];
            hu = fmaf(xu[sub][k], w, hu);
            hi = fmaf(xi[sub][k], w, hi);
        }
        const float w2 = qc_w2[j];
        rA[sub][j] = tanhf(hu) * w2;
        rB[sub][j] = tanhf(hi) * w2;
    }
    __syncthreads();
    for (int s = 32; s > 0; s >>= 1) {
        if (j < s) { rA[sub][j] += rA[sub][j + s]; rB[sub][j] += rB[sub][j + s]; }
        __syncthreads();
    }
    const float qu = rA[sub][0], qi = rB[sub][0];
    const float mx = fmaxf(qu, qi);
    const float eu = expf(qu - mx), ei = expf(qi - mx);
    const float w0 = eu / (eu + ei), w1 = ei / (eu + ei);
    const float c = w0 * xu[sub][j] + w1 * xi[sub][j];
    du[sub][j] = xu[sub][j] - c;
    di[sub][j] = xi[sub][j] - c;
    __syncthreads();

    float u2 = user_b[j], i2 = item_b[j];
#pragma unroll 8
    for (int k = 0; k < 64; k++) {
        u2 = fmaf(du[sub][k], user_w[k * 64 + j], u2);
        i2 = fmaf(di[sub][k], item_w[k * 64 + j], i2);
    }
#pragma unroll 8
    for (int k = 0; k < 64; k++) {
        const float gv = ge[sub][k];
        u2 = fmaf(gv, user_w[(64 + k) * 64 + j], u2);
        i2 = fmaf(gv, item_w[(64 + k) * 64 + j], i2);
    }
    const float m = u2 + i2 + c;
    out[N_UI * 64 + g * 64 + j] += m;
    msgf[g * 64 + j] = m;

    // block absmax
    float a = fabsf(m);
#pragma unroll
    for (int o = 16; o > 0; o >>= 1)
        a = fmaxf(a, __shfl_xor_sync(0xFFFFFFFFu, a, o));
    __shared__ float wm[8];
    const int lane = threadIdx.x & 31, wid = threadIdx.x >> 5;
    if (lane == 0) wm[wid] = a;
    __syncthreads();
    if (threadIdx.x == 0) {
        float mm = wm[0];
#pragma unroll
        for (int q = 1; q < 8; q++) mm = fmaxf(mm, wm[q]);
        atomic_fmax(amax, mm);
    }
}

// ---------------- launch ----------------
extern "C" void kernel_launch(void* const* d_in, const int* in_sizes, int n_in,
                              void* d_out, int out_size)
{
    const float* user_emb   = (const float*)d_in[0];
    const float* item_emb   = (const float*)d_in[1];
    const float* group_emb  = (const float*)d_in[2];
    const float* user_hyper = (const float*)d_in[3];
    const float* item_hyper = (const float*)d_in[4];
    const float* full_hyper = (const float*)d_in[5];
    int wbase = 6;
    if (n_in >= 15 && in_sizes[6] == 1 && in_sizes[7] == 1) wbase = 8;
    const float* qc_w1  = (const float*)d_in[wbase + 0];
    const float* qc_b1  = (const float*)d_in[wbase + 1];
    const float* qc_w2  = (const float*)d_in[wbase + 2];
    const float* user_w = (const float*)d_in[wbase + 3];
    const float* user_b = (const float*)d_in[wbase + 4];
    const float* item_w = (const float*)d_in[wbase + 5];
    const float* item_b = (const float*)d_in[wbase + 6];
    float* out = (float*)d_out;

    __half *ch, *cl, *mh, *ml;
    float *curf, *msgf, *mu, *mi, *scales;
    cudaGetSymbolAddress((void**)&ch, g_curh);
    cudaGetSymbolAddress((void**)&cl, g_curl);
    cudaGetSymbolAddress((void**)&mh, g_msgh);
    cudaGetSymbolAddress((void**)&ml, g_msgl);
    cudaGetSymbolAddress((void**)&curf, g_curf);
    cudaGetSymbolAddress((void**)&msgf, g_msgf);
    cudaGetSymbolAddress((void**)&mu, g_msgu);
    cudaGetSymbolAddress((void**)&mi, g_msgi);
    cudaGetSymbolAddress((void**)&scales, g_scales);

    cudaFuncSetAttribute(gemm_mma<true>,  cudaFuncAttributeMaxDynamicSharedMemorySize, SM_TOT);
    cudaFuncSetAttribute(gemm_mma<false>, cudaFuncAttributeMaxDynamicSharedMemorySize, SM_TOT);

    // zero scales + msgs, then init (cur fp32 + absmax), then cur planes
    zero_msgs<<<(G_CNT * 64 + 255) / 256, 256>>>(mu, mi, scales);
    init_all<<<(N_TOT * 64 + 255) / 256, 256>>>(user_emb, item_emb, group_emb, out,
                                                curf, &scales[0]);
    conv_plane<<<4096, 256>>>(curf, ch, cl, N_UI * 64, &scales[0], &scales[1]);

    for (int l = 0; l < 2; l++) {
        zero_msgs<<<(G_CNT * 64 + 255) / 256, 256>>>(mu, mi, scales);

        // msg_u = user_hyper @ cur[:U]      (split-K x18, atomics)
        gemm_mma<true><<<dim3(16, 18), 512, SM_TOT>>>(
            user_hyper, ch, cl, mu, nullptr, nullptr, nullptr, &scales[1],
            G_CNT, U_CNT, 1728);
        // msg_i = item_hyper @ cur[U:]
        gemm_mma<true><<<dim3(16, 18), 512, SM_TOT>>>(
            item_hyper, ch + (size_t)U_CNT * 64, cl + (size_t)U_CNT * 64,
            mi, nullptr, nullptr, nullptr, &scales[1],
            G_CNT, I_CNT, 3392);
        // attention + MLPs -> msg fp32 + absmax ; out_he += msg
        group_kernel<<<G_CNT / 4, 256>>>(mu, mi, group_emb,
            qc_w1 + l * 64 * 64, qc_b1 + l * 64, qc_w2 + l * 64,
            user_w + l * 128 * 64, user_b + l * 64,
            item_w + l * 128 * 64, item_b + l * 64, msgf, out, &scales[2]);
        // msg planes
        conv_plane<<<512, 256>>>(msgf, mh, ml, G_CNT * 64, &scales[2], &scales[3]);
        // node_emb = full_hyper @ msg ; out += ; cur fp32 + absmax
        gemm_mma<false><<<dim3(704, 1), 512, SM_TOT>>>(
            full_hyper, mh, ml, nullptr, out, curf, &scales[0], &scales[3],
            N_UI, G_CNT, 2048);
        // cur planes for next layer
        if (l == 0)
            conv_plane<<<4096, 256>>>(curf, ch, cl, N_UI * 64, &scales[0], &scales[1]);
    }
    (void)in_sizes; (void)n_in; (void)out_size;
}